// round 2
// baseline (speedup 1.0000x reference)
#include <cuda_runtime.h>

#define BATCH 64
#define TT 1024
#define DD 512
#define HH 512
#define J4 2048           // 4*H
#define GRID_R 128        // recurrent grid (<=148 SMs -> co-resident, barrier safe)

typedef unsigned long long u64;

// packed fp32x2 FMA (sm_103a FFMA2): d = a*b + d on both lanes
__device__ __forceinline__ void fma2(u64 &d, u64 a, u64 b) {
    asm("fma.rn.f32x2 %0, %1, %2, %0;" : "+l"(d) : "l"(a), "l"(b));
}
__device__ __forceinline__ float f2lo(u64 v) { return __uint_as_float((unsigned)v); }
__device__ __forceinline__ float f2hi(u64 v) { return __uint_as_float((unsigned)(v >> 32)); }

// Scratch (static device memory; no runtime allocation)
__device__ float g_xwi[(size_t)BATCH * TT * J4];      // [m][j], m = b*T + t  (512 MB)
__device__ float g_whp[(size_t)GRID_R * 512 * 32];    // [bu][k][ut][g][2] duplicated (8 MB)
__device__ float g_h[2][HH][BATCH];                   // double-buffered h, [u][b]
__device__ unsigned long long g_bar;

// ---------------------------------------------------------------------------
__global__ void reset_bar_kernel() { g_bar = 0ULL; }

// Repack Wh[k][g*512 + bu*4 + ut] -> duplicated pairs g_whp[bu][k][ut][g][2]
__global__ void pack_wh_kernel(const float* __restrict__ Wh) {
    int i  = blockIdx.x * 256 + threadIdx.x;     // 2,097,152 total
    int g  = (i >> 1) & 3;
    int ut = (i >> 3) & 3;
    int k  = (i >> 5) & 511;
    int bu = i >> 14;
    g_whp[i] = Wh[(size_t)k * J4 + g * 512 + bu * 4 + ut];
}

// ---------------------------------------------------------------------------
// GEMM: g_xwi[m][j] = sum_k X[m][k]*Wi[k][j] + bias[j]
// BM=128, BN=64, BK=16; 256 threads; thread tile 8m x 4j via FFMA2 (m-pairs)
__global__ __launch_bounds__(256) void gemm_xwi_kernel(
    const float* __restrict__ X, const float* __restrict__ Wi,
    const float* __restrict__ bias)
{
    __shared__ float sa[16 * 128];        // [k][m]
    __shared__ float sbd[16 * 64 * 2];    // [k][j][2] duplicated

    const int nBase = blockIdx.x * 64;
    const int mBase = blockIdx.y * 128;
    const int t  = threadIdx.x;
    const int tx = t & 15;           // j tile
    const int ty = t >> 4;           // m tile

    const int am = t & 127;
    const int ak = (t >> 7) * 8;
    const int bk = t >> 4;
    const int bj = (t & 15) * 4;

    u64 acc2[4][4];
#pragma unroll
    for (int i = 0; i < 4; i++)
#pragma unroll
        for (int j = 0; j < 4; j++) acc2[i][j] = 0ULL;

    for (int k0 = 0; k0 < 512; k0 += 16) {
        float4 a0 = *(const float4*)&X[(size_t)(mBase + am) * DD + k0 + ak];
        float4 a1 = *(const float4*)&X[(size_t)(mBase + am) * DD + k0 + ak + 4];
        float4 bv = *(const float4*)&Wi[(size_t)(k0 + bk) * J4 + nBase + bj];
        __syncthreads();
        sa[(ak + 0) * 128 + am] = a0.x;
        sa[(ak + 1) * 128 + am] = a0.y;
        sa[(ak + 2) * 128 + am] = a0.z;
        sa[(ak + 3) * 128 + am] = a0.w;
        sa[(ak + 4) * 128 + am] = a1.x;
        sa[(ak + 5) * 128 + am] = a1.y;
        sa[(ak + 6) * 128 + am] = a1.z;
        sa[(ak + 7) * 128 + am] = a1.w;
        *(float4*)&sbd[(bk * 64 + bj) * 2]     = make_float4(bv.x, bv.x, bv.y, bv.y);
        *(float4*)&sbd[(bk * 64 + bj) * 2 + 4] = make_float4(bv.z, bv.z, bv.w, bv.w);
        __syncthreads();
#pragma unroll
        for (int k = 0; k < 16; k++) {
            ulonglong2 bA = *(ulonglong2*)&sbd[(k * 64 + tx * 4) * 2];      // (b0,b0),(b1,b1)
            ulonglong2 bB = *(ulonglong2*)&sbd[(k * 64 + tx * 4) * 2 + 4];  // (b2,b2),(b3,b3)
            ulonglong2 aA = *(ulonglong2*)&sa[k * 128 + ty * 8];            // (m0,m1),(m2,m3)
            ulonglong2 aB = *(ulonglong2*)&sa[k * 128 + ty * 8 + 4];
            u64 a2[4] = {aA.x, aA.y, aB.x, aB.y};
            u64 b2[4] = {bA.x, bA.y, bB.x, bB.y};
#pragma unroll
            for (int i = 0; i < 4; i++)
#pragma unroll
                for (int j = 0; j < 4; j++)
                    fma2(acc2[i][j], a2[i], b2[j]);
        }
    }

    float4 bb = *(const float4*)&bias[nBase + tx * 4];
#pragma unroll
    for (int i2 = 0; i2 < 4; i2++) {
        float4 lo, hi;
        lo.x = f2lo(acc2[i2][0]) + bb.x;  hi.x = f2hi(acc2[i2][0]) + bb.x;
        lo.y = f2lo(acc2[i2][1]) + bb.y;  hi.y = f2hi(acc2[i2][1]) + bb.y;
        lo.z = f2lo(acc2[i2][2]) + bb.z;  hi.z = f2hi(acc2[i2][2]) + bb.z;
        lo.w = f2lo(acc2[i2][3]) + bb.w;  hi.w = f2hi(acc2[i2][3]) + bb.w;
        size_t r0 = (size_t)(mBase + ty * 8 + i2 * 2) * J4 + nBase + tx * 4;
        *(float4*)&g_xwi[r0]      = lo;
        *(float4*)&g_xwi[r0 + J4] = hi;
    }
}

// ---------------------------------------------------------------------------
__device__ __forceinline__ void grid_barrier(unsigned long long target) {
    __threadfence();
    __syncthreads();
    if (threadIdx.x == 0) {
        atomicAdd(&g_bar, 1ULL);
        while (*(volatile unsigned long long*)&g_bar < target) {
            __nanosleep(40);
        }
        __threadfence();
    }
    __syncthreads();
}

__device__ __forceinline__ float sigf(float x) {
    return 1.0f / (1.0f + __expf(-x));
}
__device__ __forceinline__ float tanhfast(float x) {
    float e = __expf(2.0f * x);
    return 1.0f - 2.0f / (e + 1.0f);
}

// Persistent scan. Block bu owns units [bu*4, bu*4+4), all gates, all batches.
// Thread: bt = batch-octet, ut = unit-in-block, kq = k-split (8-way).
// Dynamic smem: swf[16384] (full Wh slice, duplicated) | sh[8192] | csh[256]
__global__ __launch_bounds__(256) void lstm_scan_kernel(
    const float* __restrict__ c0, const float* __restrict__ h0,
    float* __restrict__ out)
{
    extern __shared__ float smem[];
    float* swf = smem;             // 16384 floats (64 KB): [k][ut][g][2]
    float* sh  = smem + 16384;     // 8192 floats (32 KB): h chunk / reduction
    float* csh = smem + 24576;     // 256 floats

    const int bu = blockIdx.x;
    const int u_base = bu * 4;
    const int tid = threadIdx.x;
    const int bt = tid & 7;
    const int ut = (tid >> 3) & 3;
    const int kq = tid >> 5;
    const int au = tid >> 6;
    const int ab = tid & 63;

    // load full duplicated Wh slice once (64 KB)
    {
        const float4* wsrc = (const float4*)(g_whp + (size_t)bu * 16384);
        float4* wd = (float4*)swf;
#pragma unroll
        for (int r = 0; r < 16; r++) wd[tid + 256 * r] = wsrc[tid + 256 * r];
    }

    csh[au * 64 + ab] = c0[ab * HH + u_base + au];
    g_h[0][u_base + au][ab] = h0[ab * HH + u_base + au];
    grid_barrier((unsigned long long)GRID_R);

    float* ys = out + 2 * BATCH * HH;

    for (int s = 0; s < TT; s++) {
        const int ph = s & 1;

        const float* xrow = g_xwi + ((size_t)ab * TT + s) * J4 + u_base + au;
        float xw0 = __ldg(xrow + 0 * 512);
        float xw1 = __ldg(xrow + 1 * 512);
        float xw2 = __ldg(xrow + 2 * 512);
        float xw3 = __ldg(xrow + 3 * 512);

        u64 acc2[4][4];   // [gate][batch-pair], pairs = batches bt*8+2p, +2p+1
#pragma unroll
        for (int g = 0; g < 4; g++)
#pragma unroll
            for (int p = 0; p < 4; p++) acc2[g][p] = 0ULL;

        const float4* hs = (const float4*)&g_h[ph][0][0];
        float4 hreg[8];
#pragma unroll
        for (int r = 0; r < 8; r++) hreg[r] = hs[tid + 256 * r];   // chunk 0

#pragma unroll 1
        for (int c = 0; c < 4; c++) {
            __syncthreads();     // sh free from previous use
            float4* shd = (float4*)sh;
#pragma unroll
            for (int r = 0; r < 8; r++) shd[tid + 256 * r] = hreg[r];
            __syncthreads();
            if (c < 3) {
#pragma unroll
                for (int r = 0; r < 8; r++)
                    hreg[r] = hs[(c + 1) * 2048 + tid + 256 * r];   // prefetch next chunk
            }
#pragma unroll
            for (int kk2 = 0; kk2 < 16; kk2++) {
                const int kk = kq * 16 + kk2;
                const float* wrow = swf + ((c * 128 + kk) * 4 + ut) * 8;
                ulonglong2 wA = *(const ulonglong2*)wrow;        // (g0,g0),(g1,g1)
                ulonglong2 wB = *(const ulonglong2*)(wrow + 4);  // (g2,g2),(g3,g3)
                ulonglong2 hA = *(const ulonglong2*)&sh[kk * 64 + bt * 8];
                ulonglong2 hB = *(const ulonglong2*)&sh[kk * 64 + bt * 8 + 4];
                u64 w2[4] = {wA.x, wA.y, wB.x, wB.y};
                u64 h2[4] = {hA.x, hA.y, hB.x, hB.y};
#pragma unroll
                for (int g = 0; g < 4; g++)
#pragma unroll
                    for (int p = 0; p < 4; p++)
                        fma2(acc2[g][p], w2[g], h2[p]);
            }
        }
        __syncthreads();   // compute done before sh reused for reduction

        // k-split reduction via shared: sred[kq][g][ut][b]
#pragma unroll
        for (int g = 0; g < 4; g++) {
            *(float4*)&sh[((kq * 4 + g) * 4 + ut) * 64 + bt * 8] =
                make_float4(f2lo(acc2[g][0]), f2hi(acc2[g][0]),
                            f2lo(acc2[g][1]), f2hi(acc2[g][1]));
            *(float4*)&sh[((kq * 4 + g) * 4 + ut) * 64 + bt * 8 + 4] =
                make_float4(f2lo(acc2[g][2]), f2hi(acc2[g][2]),
                            f2lo(acc2[g][3]), f2hi(acc2[g][3]));
        }
        __syncthreads();

        float si = xw0, sf = xw1, sg = xw2, so = xw3;
#pragma unroll
        for (int q = 0; q < 8; q++) {
            si += sh[((q * 4 + 0) * 4 + au) * 64 + ab];
            sf += sh[((q * 4 + 1) * 4 + au) * 64 + ab];
            sg += sh[((q * 4 + 2) * 4 + au) * 64 + ab];
            so += sh[((q * 4 + 3) * 4 + au) * 64 + ab];
        }
        float ig = sigf(si);
        float fg = sigf(sf);
        float gg = tanhfast(sg);
        float og = sigf(so);
        float cold = csh[au * 64 + ab];
        float cnew = fg * cold + ig * gg;
        float hnew = og * tanhfast(cnew);
        csh[au * 64 + ab] = cnew;

        g_h[ph ^ 1][u_base + au][ab] = hnew;
        ys[((size_t)ab * TT + s) * HH + u_base + au] = hnew;
        if (s == TT - 1) {
            out[ab * HH + u_base + au] = cnew;                 // cT
            out[BATCH * HH + ab * HH + u_base + au] = hnew;    // hT
        }

        if (s < TT - 1) {
            grid_barrier((unsigned long long)(s + 2) * GRID_R);
        }
    }
}

// ---------------------------------------------------------------------------
extern "C" void kernel_launch(void* const* d_in, const int* in_sizes, int n_in,
                              void* d_out, int out_size) {
    const float* x    = (const float*)d_in[0];   // [64][1024][512]
    const float* c0   = (const float*)d_in[1];   // [64][512]
    const float* h0   = (const float*)d_in[2];   // [64][512]
    const float* Wi   = (const float*)d_in[3];   // [512][2048]
    const float* Wh   = (const float*)d_in[4];   // [512][2048]
    const float* bias = (const float*)d_in[5];   // [2048]
    float* out = (float*)d_out;                  // cT | hT | ys

    static const int SMEM_SCAN = (16384 + 8192 + 256) * 4;   // 99,328 B
    cudaFuncSetAttribute(lstm_scan_kernel,
                         cudaFuncAttributeMaxDynamicSharedMemorySize, SMEM_SCAN);

    pack_wh_kernel<<<8192, 256>>>(Wh);
    gemm_xwi_kernel<<<dim3(32, 512), 256>>>(x, Wi, bias);
    reset_bar_kernel<<<1, 1>>>();
    lstm_scan_kernel<<<GRID_R, 256, SMEM_SCAN>>>(c0, h0, out);
}

// round 3
// speedup vs baseline: 1.4126x; 1.4126x over previous
#include <cuda_runtime.h>

#define BATCH 64
#define TT 1024
#define DD 512
#define HH 512
#define J4 2048
#define GRID_R 128        // scan grid (<=148 SMs -> co-resident, barrier safe)

// Scratch (static device memory; no runtime allocation)
__device__ float g_xwt[(size_t)TT * 128 * 64 * 16];   // [t][bu][ab][ut][g]  512 MB
__device__ float g_whp[(size_t)GRID_R * 512 * 16];    // [bu][k][ut][g]      4 MB
__device__ float g_h[2][HH][BATCH];                   // double-buffered h, [u][b]
__device__ unsigned g_count;
__device__ volatile unsigned g_flag;

// ---------------------------------------------------------------------------
__global__ void reset_bar_kernel() { g_count = 0u; g_flag = 0u; }

// Repack Wh[k][g*512 + bu*4 + ut] -> g_whp[bu][k][ut][g]
__global__ void pack_wh_kernel(const float* __restrict__ Wh) {
    int d  = blockIdx.x * 256 + threadIdx.x;     // 1,048,576 total
    int g  = d & 3;
    int ut = (d >> 2) & 3;
    int k  = (d >> 4) & 511;
    int bu = d >> 13;
    g_whp[d] = Wh[(size_t)k * J4 + g * 512 + bu * 4 + ut];
}

// ---------------------------------------------------------------------------
// GEMM: xwt = X @ Wi + b, written in scan-friendly transposed layout.
// BM=128, BN=128, BK=16; 256 threads; 8x8 microtile.
__global__ __launch_bounds__(256) void gemm_xwi_kernel(
    const float* __restrict__ X, const float* __restrict__ Wi,
    const float* __restrict__ bias)
{
    __shared__ float sa[16 * 128];   // [k][m]
    __shared__ float sb[16 * 128];   // [k][j]

    const int nBase = blockIdx.x * 128;
    const int mBase = blockIdx.y * 128;
    const int t  = threadIdx.x;
    const int tx = t & 15;
    const int ty = t >> 4;

    const int am  = t & 127;
    const int aks = (t >> 7) * 8;
    const int brow = t >> 5;         // 0..7
    const int bcol = (t & 31) * 4;

    float acc[8][8];
#pragma unroll
    for (int i = 0; i < 8; i++)
#pragma unroll
        for (int j = 0; j < 8; j++) acc[i][j] = 0.f;

    for (int k0 = 0; k0 < 512; k0 += 16) {
        float4 a0 = *(const float4*)&X[(size_t)(mBase + am) * DD + k0 + aks];
        float4 a1 = *(const float4*)&X[(size_t)(mBase + am) * DD + k0 + aks + 4];
        float4 b0 = *(const float4*)&Wi[(size_t)(k0 + brow) * J4 + nBase + bcol];
        float4 b1 = *(const float4*)&Wi[(size_t)(k0 + 8 + brow) * J4 + nBase + bcol];
        __syncthreads();
        sa[(aks + 0) * 128 + am] = a0.x;
        sa[(aks + 1) * 128 + am] = a0.y;
        sa[(aks + 2) * 128 + am] = a0.z;
        sa[(aks + 3) * 128 + am] = a0.w;
        sa[(aks + 4) * 128 + am] = a1.x;
        sa[(aks + 5) * 128 + am] = a1.y;
        sa[(aks + 6) * 128 + am] = a1.z;
        sa[(aks + 7) * 128 + am] = a1.w;
        *(float4*)&sb[brow * 128 + bcol]       = b0;
        *(float4*)&sb[(brow + 8) * 128 + bcol] = b1;
        __syncthreads();
#pragma unroll
        for (int k = 0; k < 16; k++) {
            float4 bA = *(float4*)&sb[k * 128 + tx * 8];
            float4 bB = *(float4*)&sb[k * 128 + tx * 8 + 4];
            float4 aA = *(float4*)&sa[k * 128 + ty * 8];
            float4 aB = *(float4*)&sa[k * 128 + ty * 8 + 4];
            float av[8] = {aA.x, aA.y, aA.z, aA.w, aB.x, aB.y, aB.z, aB.w};
            float bv[8] = {bA.x, bA.y, bA.z, bA.w, bB.x, bB.y, bB.z, bB.w};
#pragma unroll
            for (int i = 0; i < 8; i++)
#pragma unroll
                for (int j = 0; j < 8; j++)
                    acc[i][j] += av[i] * bv[j];
        }
    }

    // bias + transposed scatter: j -> (g = j>>9, u = j&511), dst offset
    // t*131072 + (u>>2)*1024 + b*16 + (u&3)*4 + g
    float4 bb0 = __ldg((const float4*)&bias[nBase + tx * 8]);
    float4 bb1 = __ldg((const float4*)&bias[nBase + tx * 8 + 4]);
    float bbv[8] = {bb0.x, bb0.y, bb0.z, bb0.w, bb1.x, bb1.y, bb1.z, bb1.w};

    const int b = mBase >> 10;            // batch (mBase is 128-aligned, T=1024)
    size_t col_off[8];
#pragma unroll
    for (int jj = 0; jj < 8; jj++) {
        int j = nBase + tx * 8 + jj;
        int u = j & 511;
        int g = j >> 9;
        col_off[jj] = (size_t)(u >> 2) * 1024 + (size_t)(u & 3) * 4 + g;
    }
#pragma unroll
    for (int i = 0; i < 8; i++) {
        int trow = (mBase & 1023) + ty * 8 + i;
        size_t base = (size_t)trow * 131072 + (size_t)b * 16;
#pragma unroll
        for (int jj = 0; jj < 8; jj++)
            g_xwt[base + col_off[jj]] = acc[i][jj] + bbv[jj];
    }
}

// ---------------------------------------------------------------------------
__device__ __forceinline__ float4 ldg_cg4(const float4* p) {
    float4 v;
    asm volatile("ld.global.cg.v4.f32 {%0,%1,%2,%3}, [%4];"
                 : "=f"(v.x), "=f"(v.y), "=f"(v.z), "=f"(v.w) : "l"(p));
    return v;
}

__device__ __forceinline__ void gbar(unsigned idx) {
    __syncthreads();
    if (threadIdx.x == 0) {
        __threadfence();
        unsigned a = atomicAdd(&g_count, 1u) + 1u;
        if (a == idx * GRID_R) {
            g_flag = idx;                         // release
        } else {
            while (g_flag < idx) __nanosleep(32);
            __threadfence();
        }
    }
    __syncthreads();
}

__device__ __forceinline__ float sigf(float x) {
    return 1.0f / (1.0f + __expf(-x));
}
__device__ __forceinline__ float tanhfast(float x) {
    float e = __expf(2.0f * x);
    return 1.0f - 2.0f / (e + 1.0f);
}

// Persistent scan. Block bu owns units [bu*4, bu*4+4), all gates, all batches.
// 512 threads: bt4 = batch-quad (4 batches), ut = unit, kq = k-split (8-way).
// Dynamic smem: hb0|hb1 (8192 each), wb0|wb1 (2048 each), csh (256); sred=hb0.
__global__ __launch_bounds__(512) void lstm_scan_kernel(
    const float* __restrict__ c0, const float* __restrict__ h0,
    float* __restrict__ out)
{
    extern __shared__ float smem[];
    float* hb[2] = {smem, smem + 8192};
    float* wb[2] = {smem + 16384, smem + 18432};
    float* sred  = smem;                  // reuse hb0 after last chunk
    float* csh   = smem + 20480;          // 256 floats

    const int bu = blockIdx.x;
    const int u_base = bu * 4;
    const int tid = threadIdx.x;
    const int bt4 = tid & 15;
    const int ut  = (tid >> 4) & 3;
    const int kq  = tid >> 6;
    const int au  = tid & 3;              // activation phase (tid<256)
    const int ab  = tid >> 2;

    if (tid < 256) {
        csh[ab * 4 + au] = c0[ab * HH + u_base + au];
        g_h[0][u_base + au][ab] = h0[ab * HH + u_base + au];
    }
    unsigned bidx = 1;
    gbar(bidx++);

    const float4* whp_blk = (const float4*)(g_whp + (size_t)bu * 8192);
    float* ys = out + 2 * BATCH * HH;

    for (int s = 0; s < TT; s++) {
        const int ph = s & 1;

        // gate prefetch: one coalesced float4 (i,f,g,o) per activation slot
        float4 xw = make_float4(0.f, 0.f, 0.f, 0.f);
        if (tid < 256)
            xw = __ldg((const float4*)g_xwt +
                       ((size_t)(s * 128 + bu) * 64 + ab) * 4 + au);

        const float4* hsrc = (const float4*)&g_h[ph][0][0];   // 2048 float4

        // fill chunk 0
        {
            float4 h0r = ldg_cg4(hsrc + tid);
            float4 h1r = ldg_cg4(hsrc + tid + 512);
            float4 h2r = ldg_cg4(hsrc + tid + 1024);
            float4 h3r = ldg_cg4(hsrc + tid + 1536);
            float4 wv  = ldg_cg4(whp_blk + tid);
            float4* hd = (float4*)hb[0];
            hd[tid]        = h0r;
            hd[tid + 512]  = h1r;
            hd[tid + 1024] = h2r;
            hd[tid + 1536] = h3r;
            ((float4*)wb[0])[tid] = wv;
        }
        __syncthreads();

        float acc[4][4];   // [gate][batch-in-quad]
#pragma unroll
        for (int g = 0; g < 4; g++)
#pragma unroll
            for (int b4 = 0; b4 < 4; b4++) acc[g][b4] = 0.f;

#pragma unroll
        for (int c = 0; c < 4; c++) {
            const float* hc = hb[c & 1];
            const float* wc = wb[c & 1];

            float4 pa, pb, pc2, pd, pw;
            if (c < 3) {
                int base = (c + 1) * 2048;
                pa = ldg_cg4(hsrc + base + tid);
                pb = ldg_cg4(hsrc + base + tid + 512);
                pc2 = ldg_cg4(hsrc + base + tid + 1024);
                pd = ldg_cg4(hsrc + base + tid + 1536);
                pw = ldg_cg4(whp_blk + (c + 1) * 512 + tid);
            }
#pragma unroll
            for (int kk2 = 0; kk2 < 16; kk2++) {
                const int kk = kq * 16 + kk2;
                float4 w4 = *(const float4*)&wc[kk * 16 + ut * 4];
                float4 h4 = *(const float4*)&hc[kk * 64 + bt4 * 4];
                float wg[4] = {w4.x, w4.y, w4.z, w4.w};
                float hv[4] = {h4.x, h4.y, h4.z, h4.w};
#pragma unroll
                for (int g = 0; g < 4; g++)
#pragma unroll
                    for (int b4 = 0; b4 < 4; b4++)
                        acc[g][b4] += wg[g] * hv[b4];
            }
            if (c < 3) {
                float4* hn = (float4*)hb[(c + 1) & 1];
                hn[tid]        = pa;
                hn[tid + 512]  = pb;
                hn[tid + 1024] = pc2;
                hn[tid + 1536] = pd;
                ((float4*)wb[(c + 1) & 1])[tid] = pw;
                __syncthreads();
            }
        }

        // k-split partials: sred[kq][g][ut][64 b] (reuses hb0; safe, chunk3 reads hb1)
#pragma unroll
        for (int g = 0; g < 4; g++)
            *(float4*)&sred[((kq * 4 + g) * 4 + ut) * 64 + bt4 * 4] =
                make_float4(acc[g][0], acc[g][1], acc[g][2], acc[g][3]);
        __syncthreads();

        if (tid < 256) {
            float si = xw.x, sf = xw.y, sg = xw.z, so = xw.w;
#pragma unroll
            for (int q = 0; q < 8; q++) {
                si += sred[((q * 4 + 0) * 4 + au) * 64 + ab];
                sf += sred[((q * 4 + 1) * 4 + au) * 64 + ab];
                sg += sred[((q * 4 + 2) * 4 + au) * 64 + ab];
                so += sred[((q * 4 + 3) * 4 + au) * 64 + ab];
            }
            float ig = sigf(si);
            float fg = sigf(sf);
            float gg = tanhfast(sg);
            float og = sigf(so);
            float cold = csh[ab * 4 + au];
            float cnew = fg * cold + ig * gg;
            float hnew = og * tanhfast(cnew);
            csh[ab * 4 + au] = cnew;

            g_h[ph ^ 1][u_base + au][ab] = hnew;
            ys[((size_t)ab * TT + s) * HH + u_base + au] = hnew;
            if (s == TT - 1) {
                out[ab * HH + u_base + au] = cnew;                 // cT
                out[BATCH * HH + ab * HH + u_base + au] = hnew;    // hT
            }
        }

        if (s < TT - 1) gbar(bidx++);
    }
}

// ---------------------------------------------------------------------------
extern "C" void kernel_launch(void* const* d_in, const int* in_sizes, int n_in,
                              void* d_out, int out_size) {
    const float* x    = (const float*)d_in[0];   // [64][1024][512]
    const float* c0   = (const float*)d_in[1];   // [64][512]
    const float* h0   = (const float*)d_in[2];   // [64][512]
    const float* Wi   = (const float*)d_in[3];   // [512][2048]
    const float* Wh   = (const float*)d_in[4];   // [512][2048]
    const float* bias = (const float*)d_in[5];   // [2048]
    float* out = (float*)d_out;                  // cT | hT | ys

    static const int SMEM_SCAN = (20480 + 256) * 4;   // 82,944 B
    cudaFuncSetAttribute(lstm_scan_kernel,
                         cudaFuncAttributeMaxDynamicSharedMemorySize, SMEM_SCAN);

    pack_wh_kernel<<<4096, 256>>>(Wh);
    gemm_xwi_kernel<<<dim3(16, 512), 256>>>(x, Wi, bias);
    reset_bar_kernel<<<1, 1>>>();
    lstm_scan_kernel<<<GRID_R, 512, SMEM_SCAN>>>(c0, h0, out);
}

// round 5
// speedup vs baseline: 1.7362x; 1.2291x over previous
#include <cuda_runtime.h>
#include <cuda_bf16.h>
#include <cstdint>

#define BATCH 64
#define TT 1024
#define DD 512
#define HH 512
#define J4 2048
#define GRID_R 128        // scan grid (<=148 SMs -> co-resident, barrier safe)

// Scratch (static device memory; no runtime allocation)
__device__ float g_xwt[(size_t)TT * 128 * 64 * 16];   // [t][bu][ab][ut][g]  512 MB
__device__ __nv_bfloat16 g_wib_hi[(size_t)J4 * DD];   // [n][k] bf16 hi      2 MB
__device__ __nv_bfloat16 g_wib_lo[(size_t)J4 * DD];   // [n][k] bf16 lo      2 MB
__device__ float g_whp[(size_t)GRID_R * 512 * 16];    // [bu][k][ut][g]      4 MB
__device__ float g_h[2][HH][BATCH];                   // double-buffered h, [u][b]
__device__ unsigned g_count;
__device__ volatile unsigned g_flag;

// ---------------------------------------------------------------------------
__global__ void reset_bar_kernel() { g_count = 0u; g_flag = 0u; }

// Wi[k][n] -> bf16 hi/lo split, transposed [n][k]
__global__ void pack_wi_kernel(const float* __restrict__ Wi) {
    int i = blockIdx.x * 256 + threadIdx.x;      // n*512 + k, 1,048,576 total
    int k = i & 511;
    int n = i >> 9;
    float w = Wi[(size_t)k * J4 + n];
    __nv_bfloat16 hi = __float2bfloat16(w);
    __nv_bfloat16 lo = __float2bfloat16(w - __bfloat162float(hi));
    g_wib_hi[i] = hi;
    g_wib_lo[i] = lo;
}

// Repack Wh[k][g*512 + bu*4 + ut] -> g_whp[bu][k][ut][g]
__global__ void pack_wh_kernel(const float* __restrict__ Wh) {
    int d  = blockIdx.x * 256 + threadIdx.x;     // 1,048,576 total
    int g  = d & 3;
    int ut = (d >> 2) & 3;
    int k  = (d >> 4) & 511;
    int bu = d >> 13;
    g_whp[d] = Wh[(size_t)k * J4 + g * 512 + bu * 4 + ut];
}

// ---------------------------------------------------------------------------
// HMMA GEMM: xwt = X @ Wi + b, bf16 hi/lo split, mma.sync.m16n8k16 (baseline PTX).
// CTA: 128m x 128n x K=512 (BK=32). 8 warps (2m x 4n), warp tile 64x32.
// ---------------------------------------------------------------------------
__device__ __forceinline__ void cvt8(const float* f, uint4& hi, uint4& lo) {
    uint32_t h[4], l[4];
#pragma unroll
    for (int j = 0; j < 4; j++) {
        __nv_bfloat16 a = __float2bfloat16(f[2 * j]);
        __nv_bfloat16 b = __float2bfloat16(f[2 * j + 1]);
        __nv_bfloat16 ra = __float2bfloat16(f[2 * j] - __bfloat162float(a));
        __nv_bfloat16 rb = __float2bfloat16(f[2 * j + 1] - __bfloat162float(b));
        __nv_bfloat162 hv; hv.x = a;  hv.y = b;
        __nv_bfloat162 lv; lv.x = ra; lv.y = rb;
        h[j] = *(uint32_t*)&hv;
        l[j] = *(uint32_t*)&lv;
    }
    hi = make_uint4(h[0], h[1], h[2], h[3]);
    lo = make_uint4(l[0], l[1], l[2], l[3]);
}

#define MMA_BF16(d, a0, a1, a2, a3, b0, b1)                                    \
    asm volatile("mma.sync.aligned.m16n8k16.row.col.f32.bf16.bf16.f32 "        \
                 "{%0,%1,%2,%3},{%4,%5,%6,%7},{%8,%9},{%0,%1,%2,%3};"          \
                 : "+f"((d)[0]), "+f"((d)[1]), "+f"((d)[2]), "+f"((d)[3])      \
                 : "r"(a0), "r"(a1), "r"(a2), "r"(a3), "r"(b0), "r"(b1))

#define RSTRIDE 80   // bytes per smem row (32 bf16 + 8 pad)

__device__ __forceinline__ void st_xwt(int m, int j, float v) {
    int b = m >> 10, trow = m & 1023, u = j & 511, g = j >> 9;
    g_xwt[(size_t)trow * 131072 + (size_t)(u >> 2) * 1024 + b * 16 + (u & 3) * 4 + g] = v;
}

__global__ __launch_bounds__(256) void gemm_hmma_kernel(
    const float* __restrict__ X, const float* __restrict__ bias)
{
    __shared__ __align__(16) char smAH[128 * RSTRIDE];
    __shared__ __align__(16) char smAL[128 * RSTRIDE];
    __shared__ __align__(16) char smBH[128 * RSTRIDE];
    __shared__ __align__(16) char smBL[128 * RSTRIDE];

    const int nBase = blockIdx.x * 128;
    const int mBase = blockIdx.y * 128;
    const int tid = threadIdx.x;
    const int wid = tid >> 5;
    const int lane = tid & 31;
    const int wm = wid >> 2;         // 0..1
    const int wn = wid & 3;          // 0..3
    const int tig = lane & 3;
    const int grp = lane >> 2;

    // fill mapping: 2 threads per row, 16 k-elems each
    const int fr = tid >> 1;
    const int fk = (tid & 1) * 16;

    float acc[4][4][4];
#pragma unroll
    for (int mt = 0; mt < 4; mt++)
#pragma unroll
        for (int nt = 0; nt < 4; nt++)
#pragma unroll
            for (int q = 0; q < 4; q++) acc[mt][nt][q] = 0.f;

    for (int ch = 0; ch < 16; ch++) {
        const int k0 = ch * 32;

        // global loads first (overlap with previous compute drain)
        const float* xr = X + (size_t)(mBase + fr) * DD + k0 + fk;
        float4 v0 = __ldg((const float4*)xr);
        float4 v1 = __ldg((const float4*)(xr + 4));
        float4 v2 = __ldg((const float4*)(xr + 8));
        float4 v3 = __ldg((const float4*)(xr + 12));
        const uint4* ph = (const uint4*)(g_wib_hi + (size_t)(nBase + fr) * 512 + k0 + fk);
        const uint4* pl = (const uint4*)(g_wib_lo + (size_t)(nBase + fr) * 512 + k0 + fk);
        uint4 bh0 = __ldg(ph), bh1 = __ldg(ph + 1);
        uint4 bl0 = __ldg(pl), bl1 = __ldg(pl + 1);

        __syncthreads();   // previous chunk's compute done
        {
            float fa[8] = {v0.x, v0.y, v0.z, v0.w, v1.x, v1.y, v1.z, v1.w};
            float fb[8] = {v2.x, v2.y, v2.z, v2.w, v3.x, v3.y, v3.z, v3.w};
            uint4 h0, l0, h1, l1;
            cvt8(fa, h0, l0);
            cvt8(fb, h1, l1);
            int off = fr * RSTRIDE + fk * 2;
            *(uint4*)(smAH + off)      = h0;
            *(uint4*)(smAH + off + 16) = h1;
            *(uint4*)(smAL + off)      = l0;
            *(uint4*)(smAL + off + 16) = l1;
            *(uint4*)(smBH + off)      = bh0;
            *(uint4*)(smBH + off + 16) = bh1;
            *(uint4*)(smBL + off)      = bl0;
            *(uint4*)(smBL + off + 16) = bl1;
        }
        __syncthreads();

#pragma unroll
        for (int ks = 0; ks < 2; ks++) {
            const int kb = ks * 16;
            // B fragments for 4 n-tiles (hi & lo)
            uint32_t bhf[4][2], blf[4][2];
#pragma unroll
            for (int nt = 0; nt < 4; nt++) {
                int row = wn * 32 + nt * 8 + grp;
                int boff = row * RSTRIDE + (kb + tig * 2) * 2;
                bhf[nt][0] = *(uint32_t*)(smBH + boff);
                bhf[nt][1] = *(uint32_t*)(smBH + boff + 16);
                blf[nt][0] = *(uint32_t*)(smBL + boff);
                blf[nt][1] = *(uint32_t*)(smBL + boff + 16);
            }
#pragma unroll
            for (int mt = 0; mt < 4; mt++) {
                int row = wm * 64 + mt * 16 + grp;
                int a0o = row * RSTRIDE + (kb + tig * 2) * 2;
                int a1o = a0o + 8 * RSTRIDE;
                uint32_t ah0 = *(uint32_t*)(smAH + a0o);
                uint32_t ah1 = *(uint32_t*)(smAH + a1o);
                uint32_t ah2 = *(uint32_t*)(smAH + a0o + 16);
                uint32_t ah3 = *(uint32_t*)(smAH + a1o + 16);
                uint32_t al0 = *(uint32_t*)(smAL + a0o);
                uint32_t al1 = *(uint32_t*)(smAL + a1o);
                uint32_t al2 = *(uint32_t*)(smAL + a0o + 16);
                uint32_t al3 = *(uint32_t*)(smAL + a1o + 16);
#pragma unroll
                for (int nt = 0; nt < 4; nt++) {
                    MMA_BF16(acc[mt][nt], ah0, ah1, ah2, ah3, bhf[nt][0], bhf[nt][1]);
                    MMA_BF16(acc[mt][nt], al0, al1, al2, al3, bhf[nt][0], bhf[nt][1]);
                    MMA_BF16(acc[mt][nt], ah0, ah1, ah2, ah3, blf[nt][0], blf[nt][1]);
                }
            }
        }
    }

    // epilogue: bias + transposed scatter into g_xwt[t][bu][ab][ut][g]
#pragma unroll
    for (int nt = 0; nt < 4; nt++) {
        int j0 = nBase + wn * 32 + nt * 8 + tig * 2;
        float bb0 = __ldg(&bias[j0]);
        float bb1 = __ldg(&bias[j0 + 1]);
#pragma unroll
        for (int mt = 0; mt < 4; mt++) {
            int m0 = mBase + wm * 64 + mt * 16 + grp;
            st_xwt(m0,     j0,     acc[mt][nt][0] + bb0);
            st_xwt(m0,     j0 + 1, acc[mt][nt][1] + bb1);
            st_xwt(m0 + 8, j0,     acc[mt][nt][2] + bb0);
            st_xwt(m0 + 8, j0 + 1, acc[mt][nt][3] + bb1);
        }
    }
}

// ---------------------------------------------------------------------------
__device__ __forceinline__ float4 ldg_cg4(const float4* p) {
    float4 v;
    asm volatile("ld.global.cg.v4.f32 {%0,%1,%2,%3}, [%4];"
                 : "=f"(v.x), "=f"(v.y), "=f"(v.z), "=f"(v.w) : "l"(p));
    return v;
}

__device__ __forceinline__ void gbar(unsigned idx) {
    __syncthreads();
    if (threadIdx.x == 0) {
        __threadfence();
        unsigned a = atomicAdd(&g_count, 1u) + 1u;
        if (a == idx * GRID_R) {
            g_flag = idx;                         // release
        } else {
            while (g_flag < idx) __nanosleep(32);
            __threadfence();
        }
    }
    __syncthreads();
}

__device__ __forceinline__ float sigf(float x) {
    return 1.0f / (1.0f + __expf(-x));
}
__device__ __forceinline__ float tanhfast(float x) {
    float e = __expf(2.0f * x);
    return 1.0f - 2.0f / (e + 1.0f);
}

// Persistent scan (unchanged from R3). Block bu owns units [bu*4, bu*4+4).
__global__ __launch_bounds__(512) void lstm_scan_kernel(
    const float* __restrict__ c0, const float* __restrict__ h0,
    float* __restrict__ out)
{
    extern __shared__ float smem[];
    float* hb[2] = {smem, smem + 8192};
    float* wb[2] = {smem + 16384, smem + 18432};
    float* sred  = smem;                  // reuse hb0 after last chunk
    float* csh   = smem + 20480;          // 256 floats

    const int bu = blockIdx.x;
    const int u_base = bu * 4;
    const int tid = threadIdx.x;
    const int bt4 = tid & 15;
    const int ut  = (tid >> 4) & 3;
    const int kq  = tid >> 6;
    const int au  = tid & 3;              // activation phase (tid<256)
    const int ab  = tid >> 2;

    if (tid < 256) {
        csh[ab * 4 + au] = c0[ab * HH + u_base + au];
        g_h[0][u_base + au][ab] = h0[ab * HH + u_base + au];
    }
    unsigned bidx = 1;
    gbar(bidx++);

    const float4* whp_blk = (const float4*)(g_whp + (size_t)bu * 8192);
    float* ys = out + 2 * BATCH * HH;

    for (int s = 0; s < TT; s++) {
        const int ph = s & 1;

        // gate prefetch: one coalesced float4 (i,f,g,o) per activation slot
        float4 xw = make_float4(0.f, 0.f, 0.f, 0.f);
        if (tid < 256)
            xw = __ldg((const float4*)g_xwt +
                       ((size_t)(s * 128 + bu) * 64 + ab) * 4 + au);

        const float4* hsrc = (const float4*)&g_h[ph][0][0];   // 2048 float4

        // fill chunk 0
        {
            float4 h0r = ldg_cg4(hsrc + tid);
            float4 h1r = ldg_cg4(hsrc + tid + 512);
            float4 h2r = ldg_cg4(hsrc + tid + 1024);
            float4 h3r = ldg_cg4(hsrc + tid + 1536);
            float4 wv  = ldg_cg4(whp_blk + tid);
            float4* hd = (float4*)hb[0];
            hd[tid]        = h0r;
            hd[tid + 512]  = h1r;
            hd[tid + 1024] = h2r;
            hd[tid + 1536] = h3r;
            ((float4*)wb[0])[tid] = wv;
        }
        __syncthreads();

        float acc[4][4];   // [gate][batch-in-quad]
#pragma unroll
        for (int g = 0; g < 4; g++)
#pragma unroll
            for (int b4 = 0; b4 < 4; b4++) acc[g][b4] = 0.f;

#pragma unroll
        for (int c = 0; c < 4; c++) {
            const float* hc = hb[c & 1];
            const float* wc = wb[c & 1];

            float4 pa, pb, pc2, pd, pw;
            if (c < 3) {
                int base = (c + 1) * 2048;
                pa = ldg_cg4(hsrc + base + tid);
                pb = ldg_cg4(hsrc + base + tid + 512);
                pc2 = ldg_cg4(hsrc + base + tid + 1024);
                pd = ldg_cg4(hsrc + base + tid + 1536);
                pw = ldg_cg4(whp_blk + (c + 1) * 512 + tid);
            }
#pragma unroll
            for (int kk2 = 0; kk2 < 16; kk2++) {
                const int kk = kq * 16 + kk2;
                float4 w4 = *(const float4*)&wc[kk * 16 + ut * 4];
                float4 h4 = *(const float4*)&hc[kk * 64 + bt4 * 4];
                float wg[4] = {w4.x, w4.y, w4.z, w4.w};
                float hv[4] = {h4.x, h4.y, h4.z, h4.w};
#pragma unroll
                for (int g = 0; g < 4; g++)
#pragma unroll
                    for (int b4 = 0; b4 < 4; b4++)
                        acc[g][b4] += wg[g] * hv[b4];
            }
            if (c < 3) {
                float4* hn = (float4*)hb[(c + 1) & 1];
                hn[tid]        = pa;
                hn[tid + 512]  = pb;
                hn[tid + 1024] = pc2;
                hn[tid + 1536] = pd;
                ((float4*)wb[(c + 1) & 1])[tid] = pw;
                __syncthreads();
            }
        }

        // k-split partials: sred[kq][g][ut][64 b]
#pragma unroll
        for (int g = 0; g < 4; g++)
            *(float4*)&sred[((kq * 4 + g) * 4 + ut) * 64 + bt4 * 4] =
                make_float4(acc[g][0], acc[g][1], acc[g][2], acc[g][3]);
        __syncthreads();

        if (tid < 256) {
            float si = xw.x, sf = xw.y, sg = xw.z, so = xw.w;
#pragma unroll
            for (int q = 0; q < 8; q++) {
                si += sred[((q * 4 + 0) * 4 + au) * 64 + ab];
                sf += sred[((q * 4 + 1) * 4 + au) * 64 + ab];
                sg += sred[((q * 4 + 2) * 4 + au) * 64 + ab];
                so += sred[((q * 4 + 3) * 4 + au) * 64 + ab];
            }
            float ig = sigf(si);
            float fg = sigf(sf);
            float gg = tanhfast(sg);
            float og = sigf(so);
            float cold = csh[ab * 4 + au];
            float cnew = fg * cold + ig * gg;
            float hnew = og * tanhfast(cnew);
            csh[ab * 4 + au] = cnew;

            g_h[ph ^ 1][u_base + au][ab] = hnew;
            ys[((size_t)ab * TT + s) * HH + u_base + au] = hnew;
            if (s == TT - 1) {
                out[ab * HH + u_base + au] = cnew;                 // cT
                out[BATCH * HH + ab * HH + u_base + au] = hnew;    // hT
            }
        }

        if (s < TT - 1) gbar(bidx++);
    }
}

// ---------------------------------------------------------------------------
extern "C" void kernel_launch(void* const* d_in, const int* in_sizes, int n_in,
                              void* d_out, int out_size) {
    const float* x    = (const float*)d_in[0];   // [64][1024][512]
    const float* c0   = (const float*)d_in[1];   // [64][512]
    const float* h0   = (const float*)d_in[2];   // [64][512]
    const float* Wi   = (const float*)d_in[3];   // [512][2048]
    const float* Wh   = (const float*)d_in[4];   // [512][2048]
    const float* bias = (const float*)d_in[5];   // [2048]
    float* out = (float*)d_out;                  // cT | hT | ys

    static const int SMEM_SCAN = (20480 + 256) * 4;   // 82,944 B
    cudaFuncSetAttribute(lstm_scan_kernel,
                         cudaFuncAttributeMaxDynamicSharedMemorySize, SMEM_SCAN);

    pack_wi_kernel<<<4096, 256>>>(Wi);
    pack_wh_kernel<<<4096, 256>>>(Wh);
    reset_bar_kernel<<<1, 1>>>();
    gemm_hmma_kernel<<<dim3(16, 512), 256>>>(x, bias);
    lstm_scan_kernel<<<GRID_R, 512, SMEM_SCAN>>>(c0, h0, out);
}

// round 6
// speedup vs baseline: 2.0846x; 1.2006x over previous
#include <cuda_runtime.h>
#include <cuda_bf16.h>
#include <cstdint>

#define BATCH 64
#define TT 1024
#define DD 512
#define HH 512
#define J4 2048
#define GRID_R 128        // scan grid (<=148 SMs -> co-resident, barrier safe)

// Scratch (static device memory; no runtime allocation)
__device__ float g_xwt[(size_t)TT * 128 * 64 * 16];   // [t][bu][ab][ut][g]  512 MB
__device__ __nv_bfloat16 g_wib_hi[(size_t)J4 * DD];   // [n][k] bf16 hi      2 MB
__device__ __nv_bfloat16 g_wib_lo[(size_t)J4 * DD];   // [n][k] bf16 lo      2 MB
__device__ __nv_bfloat16 g_whB_hi[(size_t)GRID_R * 16 * 512];  // [bu][r][k]  2 MB
__device__ __nv_bfloat16 g_whB_lo[(size_t)GRID_R * 16 * 512];  // [bu][r][k]  2 MB
__device__ __nv_bfloat16 g_hb_hi[2][BATCH * HH];      // h bf16 hi, [b][u]
__device__ __nv_bfloat16 g_hb_lo[2][BATCH * HH];      // h bf16 lo, [b][u]
__device__ unsigned g_count;
__device__ volatile unsigned g_flag;

// ---------------------------------------------------------------------------
__device__ __forceinline__ uint32_t smem_u32(const void* p) {
    uint32_t a;
    asm("{ .reg .u64 t; cvta.to.shared.u64 t, %1; cvt.u32.u64 %0, t; }"
        : "=r"(a) : "l"(p));
    return a;
}
#define CP_ASYNC16(dst, src) \
    asm volatile("cp.async.cg.shared.global [%0], [%1], 16;" :: "r"(dst), "l"(src))
#define CP_COMMIT() asm volatile("cp.async.commit_group;" ::: "memory")
#define CP_WAIT0()  asm volatile("cp.async.wait_group 0;" ::: "memory")

#define MMA_BF16(d, a0, a1, a2, a3, b0, b1)                                    \
    asm volatile("mma.sync.aligned.m16n8k16.row.col.f32.bf16.bf16.f32 "        \
                 "{%0,%1,%2,%3},{%4,%5,%6,%7},{%8,%9},{%0,%1,%2,%3};"          \
                 : "+f"((d)[0]), "+f"((d)[1]), "+f"((d)[2]), "+f"((d)[3])      \
                 : "r"(a0), "r"(a1), "r"(a2), "r"(a3), "r"(b0), "r"(b1))

// ---------------------------------------------------------------------------
__global__ void reset_bar_kernel() { g_count = 0u; g_flag = 0u; }

// Wi[k][n] -> bf16 hi/lo split, transposed [n][k]
__global__ void pack_wi_kernel(const float* __restrict__ Wi) {
    int i = blockIdx.x * 256 + threadIdx.x;      // n*512 + k
    int k = i & 511;
    int n = i >> 9;
    float w = Wi[(size_t)k * J4 + n];
    __nv_bfloat16 hi = __float2bfloat16(w);
    __nv_bfloat16 lo = __float2bfloat16(w - __bfloat162float(hi));
    g_wib_hi[i] = hi;
    g_wib_lo[i] = lo;
}

// Wh -> per-block B-operand slices: g_whB[bu][r=ut*4+g][k], bf16 hi/lo
__global__ void pack_whB_kernel(const float* __restrict__ Wh) {
    int i  = blockIdx.x * 256 + threadIdx.x;     // 1,048,576 total
    int k  = i & 511;
    int r  = (i >> 9) & 15;
    int bu = i >> 13;
    int ut = r >> 2, g = r & 3;
    float w = Wh[(size_t)k * J4 + g * 512 + bu * 4 + ut];
    __nv_bfloat16 hi = __float2bfloat16(w);
    __nv_bfloat16 lo = __float2bfloat16(w - __bfloat162float(hi));
    g_whB_hi[i] = hi;
    g_whB_lo[i] = lo;
}

// ---------------------------------------------------------------------------
// HMMA GEMM for x@Wi (unchanged from R5): 128x128xK512, 8 warps, hi/lo split.
// ---------------------------------------------------------------------------
__device__ __forceinline__ void cvt8(const float* f, uint4& hi, uint4& lo) {
    uint32_t h[4], l[4];
#pragma unroll
    for (int j = 0; j < 4; j++) {
        __nv_bfloat16 a = __float2bfloat16(f[2 * j]);
        __nv_bfloat16 b = __float2bfloat16(f[2 * j + 1]);
        __nv_bfloat16 ra = __float2bfloat16(f[2 * j] - __bfloat162float(a));
        __nv_bfloat16 rb = __float2bfloat16(f[2 * j + 1] - __bfloat162float(b));
        __nv_bfloat162 hv; hv.x = a;  hv.y = b;
        __nv_bfloat162 lv; lv.x = ra; lv.y = rb;
        h[j] = *(uint32_t*)&hv;
        l[j] = *(uint32_t*)&lv;
    }
    hi = make_uint4(h[0], h[1], h[2], h[3]);
    lo = make_uint4(l[0], l[1], l[2], l[3]);
}

#define RSTRIDE 80   // bytes per smem row (32 bf16 + 8 pad)

__device__ __forceinline__ void st_xwt(int m, int j, float v) {
    int b = m >> 10, trow = m & 1023, u = j & 511, g = j >> 9;
    g_xwt[(size_t)trow * 131072 + (size_t)(u >> 2) * 1024 + b * 16 + (u & 3) * 4 + g] = v;
}

__global__ __launch_bounds__(256) void gemm_hmma_kernel(
    const float* __restrict__ X, const float* __restrict__ bias)
{
    __shared__ __align__(16) char smAH[128 * RSTRIDE];
    __shared__ __align__(16) char smAL[128 * RSTRIDE];
    __shared__ __align__(16) char smBH[128 * RSTRIDE];
    __shared__ __align__(16) char smBL[128 * RSTRIDE];

    const int nBase = blockIdx.x * 128;
    const int mBase = blockIdx.y * 128;
    const int tid = threadIdx.x;
    const int wid = tid >> 5;
    const int lane = tid & 31;
    const int wm = wid >> 2;
    const int wn = wid & 3;
    const int tig = lane & 3;
    const int grp = lane >> 2;
    const int fr = tid >> 1;
    const int fk = (tid & 1) * 16;

    float acc[4][4][4];
#pragma unroll
    for (int mt = 0; mt < 4; mt++)
#pragma unroll
        for (int nt = 0; nt < 4; nt++)
#pragma unroll
            for (int q = 0; q < 4; q++) acc[mt][nt][q] = 0.f;

    for (int ch = 0; ch < 16; ch++) {
        const int k0 = ch * 32;
        const float* xr = X + (size_t)(mBase + fr) * DD + k0 + fk;
        float4 v0 = __ldg((const float4*)xr);
        float4 v1 = __ldg((const float4*)(xr + 4));
        float4 v2 = __ldg((const float4*)(xr + 8));
        float4 v3 = __ldg((const float4*)(xr + 12));
        const uint4* ph = (const uint4*)(g_wib_hi + (size_t)(nBase + fr) * 512 + k0 + fk);
        const uint4* pl = (const uint4*)(g_wib_lo + (size_t)(nBase + fr) * 512 + k0 + fk);
        uint4 bh0 = __ldg(ph), bh1 = __ldg(ph + 1);
        uint4 bl0 = __ldg(pl), bl1 = __ldg(pl + 1);

        __syncthreads();
        {
            float fa[8] = {v0.x, v0.y, v0.z, v0.w, v1.x, v1.y, v1.z, v1.w};
            float fb[8] = {v2.x, v2.y, v2.z, v2.w, v3.x, v3.y, v3.z, v3.w};
            uint4 h0, l0, h1, l1;
            cvt8(fa, h0, l0);
            cvt8(fb, h1, l1);
            int off = fr * RSTRIDE + fk * 2;
            *(uint4*)(smAH + off)      = h0;
            *(uint4*)(smAH + off + 16) = h1;
            *(uint4*)(smAL + off)      = l0;
            *(uint4*)(smAL + off + 16) = l1;
            *(uint4*)(smBH + off)      = bh0;
            *(uint4*)(smBH + off + 16) = bh1;
            *(uint4*)(smBL + off)      = bl0;
            *(uint4*)(smBL + off + 16) = bl1;
        }
        __syncthreads();

#pragma unroll
        for (int ks = 0; ks < 2; ks++) {
            const int kb = ks * 16;
            uint32_t bhf[4][2], blf[4][2];
#pragma unroll
            for (int nt = 0; nt < 4; nt++) {
                int row = wn * 32 + nt * 8 + grp;
                int boff = row * RSTRIDE + (kb + tig * 2) * 2;
                bhf[nt][0] = *(uint32_t*)(smBH + boff);
                bhf[nt][1] = *(uint32_t*)(smBH + boff + 16);
                blf[nt][0] = *(uint32_t*)(smBL + boff);
                blf[nt][1] = *(uint32_t*)(smBL + boff + 16);
            }
#pragma unroll
            for (int mt = 0; mt < 4; mt++) {
                int row = wm * 64 + mt * 16 + grp;
                int a0o = row * RSTRIDE + (kb + tig * 2) * 2;
                int a1o = a0o + 8 * RSTRIDE;
                uint32_t ah0 = *(uint32_t*)(smAH + a0o);
                uint32_t ah1 = *(uint32_t*)(smAH + a1o);
                uint32_t ah2 = *(uint32_t*)(smAH + a0o + 16);
                uint32_t ah3 = *(uint32_t*)(smAH + a1o + 16);
                uint32_t al0 = *(uint32_t*)(smAL + a0o);
                uint32_t al1 = *(uint32_t*)(smAL + a1o);
                uint32_t al2 = *(uint32_t*)(smAL + a0o + 16);
                uint32_t al3 = *(uint32_t*)(smAL + a1o + 16);
#pragma unroll
                for (int nt = 0; nt < 4; nt++) {
                    MMA_BF16(acc[mt][nt], ah0, ah1, ah2, ah3, bhf[nt][0], bhf[nt][1]);
                    MMA_BF16(acc[mt][nt], al0, al1, al2, al3, bhf[nt][0], bhf[nt][1]);
                    MMA_BF16(acc[mt][nt], ah0, ah1, ah2, ah3, blf[nt][0], blf[nt][1]);
                }
            }
        }
    }

#pragma unroll
    for (int nt = 0; nt < 4; nt++) {
        int j0 = nBase + wn * 32 + nt * 8 + tig * 2;
        float bb0 = __ldg(&bias[j0]);
        float bb1 = __ldg(&bias[j0 + 1]);
#pragma unroll
        for (int mt = 0; mt < 4; mt++) {
            int m0 = mBase + wm * 64 + mt * 16 + grp;
            st_xwt(m0,     j0,     acc[mt][nt][0] + bb0);
            st_xwt(m0,     j0 + 1, acc[mt][nt][1] + bb1);
            st_xwt(m0 + 8, j0,     acc[mt][nt][2] + bb0);
            st_xwt(m0 + 8, j0 + 1, acc[mt][nt][3] + bb1);
        }
    }
}

// ---------------------------------------------------------------------------
__device__ __forceinline__ void gbar(unsigned idx) {
    __syncthreads();
    if (threadIdx.x == 0) {
        __threadfence();
        unsigned a = atomicAdd(&g_count, 1u) + 1u;
        if (a == idx * GRID_R) {
            g_flag = idx;                         // release
        } else {
            while (g_flag < idx) __nanosleep(32);
            __threadfence();
        }
    }
    __syncthreads();
}

__device__ __forceinline__ float sigf(float x) {
    return 1.0f / (1.0f + __expf(-x));
}
__device__ __forceinline__ float tanhfast(float x) {
    float e = __expf(2.0f * x);
    return 1.0f - 2.0f / (e + 1.0f);
}

// ---------------------------------------------------------------------------
// HMMA persistent scan. Block bu owns 16 gate-unit rows r=ut*4+g (units bu*4+ut).
// 512 threads = 16 warps: mq = batch-tile (16 b), kq = k-chunk (128 k).
// Wh B-fragments live in REGISTERS for all 1024 steps; h chunks via cp.async.
// smem: hbuf[2] (hi|lo, 64 rows x 272B each) | sD[4][64][16] f32 | csh[256]
// ---------------------------------------------------------------------------
#define HB_STRIDE 272                 // 256B row + 16 pad
#define BUF_SZ (64 * HB_STRIDE * 2)   // hi + lo = 34,816
#define SD_OFF (2 * BUF_SZ)           // 69,632
#define CSH_OFF (SD_OFF + 4 * 64 * 16 * 4)   // 86,016
#define SMEM_SCAN (CSH_OFF + 256 * 4)        // 87,040

__global__ __launch_bounds__(512, 1) void lstm_scan_kernel(
    const float* __restrict__ c0, const float* __restrict__ h0,
    float* __restrict__ out)
{
    extern __shared__ __align__(16) char sm[];
    float* sD  = (float*)(sm + SD_OFF);
    float* csh = (float*)(sm + CSH_OFF);
    const uint32_t sbase = smem_u32(sm);

    const int bu = blockIdx.x;
    const int u_base = bu * 4;
    const int tid = threadIdx.x;
    const int lane = tid & 31;
    const int wid = tid >> 5;
    const int grp = lane >> 2;
    const int tig = lane & 3;
    const int mq = wid & 3;            // batch tile (16 batches)
    const int kq = wid >> 2;           // k chunk (128 k)
    const int ab = tid >> 2;           // activation batch (tid<256)
    const int au = tid & 3;            // activation unit

    // ---- Wh B fragments -> registers (constant across all steps) ----
    uint32_t bH[8][2][2], bL[8][2][2];
    {
        const __nv_bfloat16* baseH = g_whB_hi + (size_t)bu * 16 * 512;
        const __nv_bfloat16* baseL = g_whB_lo + (size_t)bu * 16 * 512;
#pragma unroll
        for (int ks = 0; ks < 8; ks++)
#pragma unroll
            for (int nt = 0; nt < 2; nt++) {
                int r = nt * 8 + grp;
                int k = kq * 128 + ks * 16 + tig * 2;
                bH[ks][nt][0] = *(const uint32_t*)(baseH + (size_t)r * 512 + k);
                bH[ks][nt][1] = *(const uint32_t*)(baseH + (size_t)r * 512 + k + 8);
                bL[ks][nt][0] = *(const uint32_t*)(baseL + (size_t)r * 512 + k);
                bL[ks][nt][1] = *(const uint32_t*)(baseL + (size_t)r * 512 + k + 8);
            }
    }

    // ---- init c and h[0] (bf16 hi/lo) ----
    if (tid < 256) {
        csh[tid] = c0[ab * HH + u_base + au];
        float hv = h0[ab * HH + u_base + au];
        __nv_bfloat16 hi = __float2bfloat16(hv);
        __nv_bfloat16 lo = __float2bfloat16(hv - __bfloat162float(hi));
        g_hb_hi[0][ab * HH + u_base + au] = hi;
        g_hb_lo[0][ab * HH + u_base + au] = lo;
    }
    unsigned bidx = 1;
    gbar(bidx++);

    float* ys = out + 2 * BATCH * HH;
    const int crow = tid >> 4;         // copy row base 0..31
    const int cseg = tid & 15;         // 16B segment

    for (int s = 0; s < TT; s++) {
        const int ph = s & 1;

        float4 xw = make_float4(0.f, 0.f, 0.f, 0.f);
        if (tid < 256)
            xw = __ldg((const float4*)g_xwt +
                       ((size_t)(s * 128 + bu) * 64 + ab) * 4 + au);

        const char* hsH = (const char*)g_hb_hi[ph];
        const char* hsL = (const char*)g_hb_lo[ph];

        // copy chunk 0
        {
            uint32_t dH = sbase;            // buf0 hi
            uint32_t dL = sbase + 64 * HB_STRIDE;
#pragma unroll
            for (int q = 0; q < 2; q++) {
                int b = crow + q * 32;
                CP_ASYNC16(dH + b * HB_STRIDE + cseg * 16, hsH + b * 1024 + cseg * 16);
                CP_ASYNC16(dL + b * HB_STRIDE + cseg * 16, hsL + b * 1024 + cseg * 16);
            }
            CP_COMMIT();
            CP_WAIT0();
        }
        __syncthreads();

        float acc[2][4];
#pragma unroll
        for (int nt = 0; nt < 2; nt++)
#pragma unroll
            for (int q = 0; q < 4; q++) acc[nt][q] = 0.f;

#pragma unroll
        for (int c = 0; c < 4; c++) {
            // prefetch chunk c+1 into the other buffer
            if (c < 3) {
                uint32_t dH = sbase + ((c + 1) & 1) * BUF_SZ;
                uint32_t dL = dH + 64 * HB_STRIDE;
                int co = (c + 1) * 256;
#pragma unroll
                for (int q = 0; q < 2; q++) {
                    int b = crow + q * 32;
                    CP_ASYNC16(dH + b * HB_STRIDE + cseg * 16, hsH + b * 1024 + co + cseg * 16);
                    CP_ASYNC16(dL + b * HB_STRIDE + cseg * 16, hsL + b * 1024 + co + cseg * 16);
                }
                CP_COMMIT();
            }
            // compute: only warps with kq == c
            if (kq == c) {
                const char* bufH = sm + (c & 1) * BUF_SZ;
                const char* bufL = bufH + 64 * HB_STRIDE;
                const int arow = mq * 16 + grp;
#pragma unroll
                for (int ks = 0; ks < 8; ks++) {
                    int aoff = arow * HB_STRIDE + (ks * 16 + tig * 2) * 2;
                    uint32_t ah0 = *(const uint32_t*)(bufH + aoff);
                    uint32_t ah1 = *(const uint32_t*)(bufH + aoff + 8 * HB_STRIDE);
                    uint32_t ah2 = *(const uint32_t*)(bufH + aoff + 16);
                    uint32_t ah3 = *(const uint32_t*)(bufH + aoff + 8 * HB_STRIDE + 16);
                    uint32_t al0 = *(const uint32_t*)(bufL + aoff);
                    uint32_t al1 = *(const uint32_t*)(bufL + aoff + 8 * HB_STRIDE);
                    uint32_t al2 = *(const uint32_t*)(bufL + aoff + 16);
                    uint32_t al3 = *(const uint32_t*)(bufL + aoff + 8 * HB_STRIDE + 16);
#pragma unroll
                    for (int nt = 0; nt < 2; nt++) {
                        MMA_BF16(acc[nt], ah0, ah1, ah2, ah3, bH[ks][nt][0], bH[ks][nt][1]);
                        MMA_BF16(acc[nt], al0, al1, al2, al3, bH[ks][nt][0], bH[ks][nt][1]);
                        MMA_BF16(acc[nt], ah0, ah1, ah2, ah3, bL[ks][nt][0], bL[ks][nt][1]);
                    }
                }
            }
            CP_WAIT0();
            __syncthreads();
        }

        // store D partials: sD[kq][b][r]
#pragma unroll
        for (int nt = 0; nt < 2; nt++) {
            float2 v01 = make_float2(acc[nt][0], acc[nt][1]);
            float2 v23 = make_float2(acc[nt][2], acc[nt][3]);
            *(float2*)&sD[((kq * 64) + mq * 16 + grp) * 16 + nt * 8 + tig * 2] = v01;
            *(float2*)&sD[((kq * 64) + mq * 16 + grp + 8) * 16 + nt * 8 + tig * 2] = v23;
        }
        __syncthreads();

        // activation (tid<256): gates are contiguous float4 (r = ut*4+g)
        if (tid < 256) {
            float4 s0 = *(float4*)&sD[(0 * 64 + ab) * 16 + au * 4];
            float4 s1 = *(float4*)&sD[(1 * 64 + ab) * 16 + au * 4];
            float4 s2 = *(float4*)&sD[(2 * 64 + ab) * 16 + au * 4];
            float4 s3 = *(float4*)&sD[(3 * 64 + ab) * 16 + au * 4];
            float si = xw.x + s0.x + s1.x + s2.x + s3.x;
            float sf = xw.y + s0.y + s1.y + s2.y + s3.y;
            float sg = xw.z + s0.z + s1.z + s2.z + s3.z;
            float so = xw.w + s0.w + s1.w + s2.w + s3.w;

            float ig = sigf(si);
            float fg = sigf(sf);
            float gg = tanhfast(sg);
            float og = sigf(so);
            float cold = csh[tid];
            float cnew = fg * cold + ig * gg;
            float hnew = og * tanhfast(cnew);
            csh[tid] = cnew;

            __nv_bfloat16 hi = __float2bfloat16(hnew);
            __nv_bfloat16 lo = __float2bfloat16(hnew - __bfloat162float(hi));
            int uo = ab * HH + u_base + au;
            g_hb_hi[ph ^ 1][uo] = hi;
            g_hb_lo[ph ^ 1][uo] = lo;

            ys[((size_t)ab * TT + s) * HH + u_base + au] = hnew;
            if (s == TT - 1) {
                out[ab * HH + u_base + au] = cnew;                 // cT
                out[BATCH * HH + ab * HH + u_base + au] = hnew;    // hT
            }
        }

        if (s < TT - 1) gbar(bidx++);
    }
}

// ---------------------------------------------------------------------------
extern "C" void kernel_launch(void* const* d_in, const int* in_sizes, int n_in,
                              void* d_out, int out_size) {
    const float* x    = (const float*)d_in[0];   // [64][1024][512]
    const float* c0   = (const float*)d_in[1];   // [64][512]
    const float* h0   = (const float*)d_in[2];   // [64][512]
    const float* Wi   = (const float*)d_in[3];   // [512][2048]
    const float* Wh   = (const float*)d_in[4];   // [512][2048]
    const float* bias = (const float*)d_in[5];   // [2048]
    float* out = (float*)d_out;                  // cT | hT | ys

    cudaFuncSetAttribute(lstm_scan_kernel,
                         cudaFuncAttributeMaxDynamicSharedMemorySize, SMEM_SCAN);

    pack_wi_kernel<<<4096, 256>>>(Wi);
    pack_whB_kernel<<<4096, 256>>>(Wh);
    reset_bar_kernel<<<1, 1>>>();
    gemm_hmma_kernel<<<dim3(16, 512), 256>>>(x, bias);
    lstm_scan_kernel<<<GRID_R, 512, SMEM_SCAN>>>(c0, h0, out);
}